// round 1
// baseline (speedup 1.0000x reference)
#include <cuda_runtime.h>
#include <cuda_bf16.h>

#define NPTS  100000
#define CIN   96
#define CHID  576
#define COUT  96
#define BM    64

// Scratch: stage-1 and stage-2 activations [N, 576] fp32 (230.4 MB each).
__device__ float g_x1[(size_t)NPTS * CHID];
__device__ float g_x2[(size_t)NPTS * CHID];

__device__ __forceinline__ float clamp128f(float x) { return fminf(fmaxf(x, -128.0f), 128.0f); }
__device__ __forceinline__ float relu6f(float x)    { return fminf(fmaxf(x, 0.0f), 6.0f); }

// ---------------------------------------------------------------------------
// Kernel 1: x1 = relu6(clamp(requant(feats @ w1 + b1, s1)))
// feats [N,96], w1 [96,576] -> x1 [N,576]
// Tile: BM=64 rows x BN=96 hid cols, BK=32 (3 chunks). 256 threads, 4x6 microtile.
// ---------------------------------------------------------------------------
__global__ __launch_bounds__(256) void k_expand(
    const float* __restrict__ feats, const float* __restrict__ w1,
    const float* __restrict__ b1,    const float* __restrict__ s1)
{
    __shared__ float As[BM * 33];   // [m][k], stride 33 to dodge bank conflicts
    __shared__ float Bs[32 * 96];   // [k][h]

    const int n0  = blockIdx.x * BM;
    const int h0  = blockIdx.y * 96;
    const int tid = threadIdx.x;
    const int tm  = tid & 15;       // 0..15 -> m = tm*4..
    const int th  = tid >> 4;       // 0..15 -> h = th*6..

    float acc[4][6];
#pragma unroll
    for (int i = 0; i < 4; i++)
#pragma unroll
        for (int j = 0; j < 6; j++) acc[i][j] = 0.0f;

    for (int k0 = 0; k0 < CIN; k0 += 32) {
        // Load A tile: 64 rows x 32 cols (float4 from gmem, scalar scatter to padded smem)
        {
            const int c4 = (tid & 7) * 4;
            const int r  = tid >> 3;            // 0..31
#pragma unroll
            for (int p = 0; p < 2; p++) {
                const int row = r + p * 32;
                const int n   = n0 + row;
                float4 v = make_float4(0.f, 0.f, 0.f, 0.f);
                if (n < NPTS)
                    v = *reinterpret_cast<const float4*>(feats + (size_t)n * CIN + k0 + c4);
                float* dst = &As[row * 33 + c4];
                dst[0] = v.x; dst[1] = v.y; dst[2] = v.z; dst[3] = v.w;
            }
        }
        // Load B tile: 32 rows x 96 cols (768 float4, 3 per thread)
#pragma unroll
        for (int p = 0; p < 3; p++) {
            const int idx = tid + p * 256;
            const int row = idx / 24;
            const int c   = (idx % 24) * 4;
            *reinterpret_cast<float4*>(&Bs[row * 96 + c]) =
                *reinterpret_cast<const float4*>(w1 + (size_t)(k0 + row) * CHID + h0 + c);
        }
        __syncthreads();

#pragma unroll
        for (int kk = 0; kk < 32; kk++) {
            float a[4], b[6];
#pragma unroll
            for (int i = 0; i < 4; i++) a[i] = As[(tm * 4 + i) * 33 + kk];
#pragma unroll
            for (int j = 0; j < 6; j++) b[j] = Bs[kk * 96 + th * 6 + j];
#pragma unroll
            for (int i = 0; i < 4; i++)
#pragma unroll
                for (int j = 0; j < 6; j++) acc[i][j] = fmaf(a[i], b[j], acc[i][j]);
        }
        __syncthreads();
    }

    // Epilogue: bias + requant + clamp + relu6 -> g_x1
#pragma unroll
    for (int j = 0; j < 6; j++) {
        const int   h  = h0 + th * 6 + j;
        const float bb = __ldg(b1 + h);
        const float m  = rintf(__ldg(s1 + h)) * 256.0f;
#pragma unroll
        for (int i = 0; i < 4; i++) {
            const int n = n0 + tm * 4 + i;
            if (n < NPTS) {
                float v = (acc[i][j] + bb) * m * (1.0f / 65536.0f);
                g_x1[(size_t)n * CHID + h] = relu6f(clamp128f(v));
            }
        }
    }
}

// ---------------------------------------------------------------------------
// Kernel 2: depthwise 3x3 sparse conv on x1 -> x2
// 576 threads/block (one channel each), 64 sites per block.
// ---------------------------------------------------------------------------
__global__ __launch_bounds__(576) void k_dw(
    const int* __restrict__ nbr, const float* __restrict__ w2,
    const float* __restrict__ b2, const float* __restrict__ s2)
{
    __shared__ int nb_s[9 * BM];   // [k][j]

    const int n0 = blockIdx.x * BM;
    const int c  = threadIdx.x;    // 0..575

    float wreg[9];
#pragma unroll
    for (int k = 0; k < 9; k++) wreg[k] = __ldg(w2 + k * CHID + c);
    const float bb = __ldg(b2 + c);
    const float m  = rintf(__ldg(s2 + c)) * 256.0f;

    {
        const int k = threadIdx.x >> 6;   // 0..8
        const int j = threadIdx.x & 63;   // 0..63
        const int n = n0 + j;
        nb_s[k * BM + j] = (n < NPTS) ? nbr[k * NPTS + n] : -1;
    }
    __syncthreads();

    const int jmax = min(BM, NPTS - n0);
    for (int j = 0; j < jmax; j++) {
        float acc = bb;
#pragma unroll
        for (int k = 0; k < 9; k++) {
            const int nb = nb_s[k * BM + j];      // uniform across block -> no divergence
            if (nb >= 0)
                acc = fmaf(g_x1[(size_t)nb * CHID + c], wreg[k], acc);
        }
        float v = acc * m * (1.0f / 65536.0f);
        g_x2[(size_t)(n0 + j) * CHID + c] = relu6f(clamp128f(v));
    }
}

// ---------------------------------------------------------------------------
// Kernel 3: out = rm * clamp(requant(x2 @ w3 + b3, s3)) + rr * feats
// x2 [N,576], w3 [576,96]. BM=64 x BN=96 (full), BK=32 (18 chunks).
// ---------------------------------------------------------------------------
__global__ __launch_bounds__(256) void k_project(
    const float* __restrict__ feats, const float* __restrict__ w3,
    const float* __restrict__ b3,    const float* __restrict__ s3,
    const float* __restrict__ s_main, const float* __restrict__ s_res,
    float* __restrict__ out)
{
    __shared__ float As[BM * 33];
    __shared__ float Bs[32 * 96];

    const int n0  = blockIdx.x * BM;
    const int tid = threadIdx.x;
    const int tm  = tid & 15;
    const int th  = tid >> 4;

    float acc[4][6];
#pragma unroll
    for (int i = 0; i < 4; i++)
#pragma unroll
        for (int j = 0; j < 6; j++) acc[i][j] = 0.0f;

    for (int k0 = 0; k0 < CHID; k0 += 32) {
        {
            const int c4 = (tid & 7) * 4;
            const int r  = tid >> 3;
#pragma unroll
            for (int p = 0; p < 2; p++) {
                const int row = r + p * 32;
                const int n   = n0 + row;
                float4 v = make_float4(0.f, 0.f, 0.f, 0.f);
                if (n < NPTS)
                    v = *reinterpret_cast<const float4*>(g_x2 + (size_t)n * CHID + k0 + c4);
                float* dst = &As[row * 33 + c4];
                dst[0] = v.x; dst[1] = v.y; dst[2] = v.z; dst[3] = v.w;
            }
        }
#pragma unroll
        for (int p = 0; p < 3; p++) {
            const int idx = tid + p * 256;
            const int row = idx / 24;
            const int c   = (idx % 24) * 4;
            *reinterpret_cast<float4*>(&Bs[row * 96 + c]) =
                *reinterpret_cast<const float4*>(w3 + (size_t)(k0 + row) * COUT + c);
        }
        __syncthreads();

#pragma unroll
        for (int kk = 0; kk < 32; kk++) {
            float a[4], b[6];
#pragma unroll
            for (int i = 0; i < 4; i++) a[i] = As[(tm * 4 + i) * 33 + kk];
#pragma unroll
            for (int j = 0; j < 6; j++) b[j] = Bs[kk * 96 + th * 6 + j];
#pragma unroll
            for (int i = 0; i < 4; i++)
#pragma unroll
                for (int j = 0; j < 6; j++) acc[i][j] = fmaf(a[i], b[j], acc[i][j]);
        }
        __syncthreads();
    }

    const float rm = rintf(__ldg(s_main)) * 256.0f;
    const float rr = rintf(__ldg(s_res)) * 256.0f;

#pragma unroll
    for (int j = 0; j < 6; j++) {
        const int   h  = th * 6 + j;
        const float bb = __ldg(b3 + h);
        const float m  = rintf(__ldg(s3 + h)) * 256.0f;
#pragma unroll
        for (int i = 0; i < 4; i++) {
            const int n = n0 + tm * 4 + i;
            if (n < NPTS) {
                float v = clamp128f((acc[i][j] + bb) * m * (1.0f / 65536.0f));
                out[(size_t)n * COUT + h] = rm * v + rr * feats[(size_t)n * CIN + h];
            }
        }
    }
}

// ---------------------------------------------------------------------------
extern "C" void kernel_launch(void* const* d_in, const int* in_sizes, int n_in,
                              void* d_out, int out_size)
{
    const float* feats = (const float*)d_in[0];
    const int*   nbr   = (const int*)  d_in[1];
    const float* w1    = (const float*)d_in[2];
    const float* b1    = (const float*)d_in[3];
    const float* w2    = (const float*)d_in[4];
    const float* b2    = (const float*)d_in[5];
    const float* w3    = (const float*)d_in[6];
    const float* b3    = (const float*)d_in[7];
    const float* s1    = (const float*)d_in[8];
    const float* s2    = (const float*)d_in[9];
    const float* s3    = (const float*)d_in[10];
    const float* smain = (const float*)d_in[11];
    const float* sres  = (const float*)d_in[12];
    float* out = (float*)d_out;

    const int mb = (NPTS + BM - 1) / BM;   // 1563

    k_expand <<<dim3(mb, CHID / 96), 256>>>(feats, w1, b1, s1);
    k_dw     <<<mb, CHID>>>(nbr, w2, b2, s2);
    k_project<<<mb, 256>>>(feats, w3, b3, s3, smain, sres, out);
}

// round 2
// speedup vs baseline: 2.4072x; 2.4072x over previous
#include <cuda_runtime.h>
#include <cuda_fp16.h>

#define NPTS  100000
#define CIN   96
#define CHID  576
#define COUT  96

// ---------------- device scratch ----------------
__device__ __half g_feats16[(size_t)NPTS * CIN];        // feats as fp16 (exact)
__device__ __half g_w1t[(size_t)CHID * CIN];            // w1^T [n][k]
__device__ __half g_w3t[(size_t)COUT * CHID];           // w3^T [n][k]
__device__ __half g_x1s[(size_t)NPTS * CHID];           // x1*256 (exact integers 0..1536)
__device__ __half g_x2h[(size_t)NPTS * CHID];           // x2 hi
__device__ __half g_x2l[(size_t)NPTS * CHID];           // x2 lo (x2 = hi+lo exact)

__device__ __forceinline__ float clamp128f(float x) { return fminf(fmaxf(x, -128.0f), 128.0f); }
__device__ __forceinline__ float relu6f(float x)    { return fminf(fmaxf(x, 0.0f), 6.0f); }

__device__ __forceinline__ void mma16816(float* c, const unsigned* a, const unsigned* b) {
    asm volatile(
        "mma.sync.aligned.m16n8k16.row.col.f32.f16.f16.f32 "
        "{%0,%1,%2,%3}, {%4,%5,%6,%7}, {%8,%9}, {%0,%1,%2,%3};\n"
        : "+f"(c[0]), "+f"(c[1]), "+f"(c[2]), "+f"(c[3])
        : "r"(a[0]), "r"(a[1]), "r"(a[2]), "r"(a[3]), "r"(b[0]), "r"(b[1]));
}

// ---------------------------------------------------------------------------
// Kernel 0: fp32 -> fp16 conversions (+ weight transposes)
// ---------------------------------------------------------------------------
__global__ __launch_bounds__(256) void k_convert(
    const float* __restrict__ feats, const float* __restrict__ w1,
    const float* __restrict__ w3)
{
    const size_t i = (size_t)blockIdx.x * blockDim.x + threadIdx.x;
    if (i < (size_t)NPTS * CIN)
        g_feats16[i] = __float2half_rn(feats[i]);
    if (i < (size_t)CIN * CHID) {      // 55296
        const int n = (int)(i / CIN), k = (int)(i % CIN);      // w1t[n][k] = w1[k][n]
        g_w1t[i] = __float2half_rn(w1[(size_t)k * CHID + n]);
        const int n3 = (int)(i / CHID), k3 = (int)(i % CHID);  // w3t[n][k] = w3[k][n]
        g_w3t[i] = __float2half_rn(w3[(size_t)k3 * COUT + n3]);
    }
}

// ---------------------------------------------------------------------------
// Kernel 1: x1s = 256 * relu6(clamp(requant(feats @ w1 + b1, s1)))   (fp16 exact)
// BM=128, BN=64, K=96 (fits smem, no k-loop). 256 thr = 8 warps (4m x 2n),
// warp tile 32x32 -> 2x4 mma frags per k-step, 6 k-steps.
// ---------------------------------------------------------------------------
#define P1 104   // padded row length in halves (stride 52 words == 20 mod 32 -> conflict-free)
__global__ __launch_bounds__(256) void k1_expand(
    const float* __restrict__ b1, const float* __restrict__ s1)
{
    __shared__ __half As[128 * P1];
    __shared__ __half Bs[64 * P1];

    const int n0 = blockIdx.x * 128;
    const int h0 = blockIdx.y * 64;
    const int tid = threadIdx.x;

    // stage A: 128 rows x 96 halves = 1536 uint4
#pragma unroll
    for (int p = 0; p < 6; p++) {
        const int idx = tid + p * 256;
        const int r = idx / 12, s = idx % 12;
        const int n = n0 + r;
        uint4 v = make_uint4(0u, 0u, 0u, 0u);
        if (n < NPTS) v = *reinterpret_cast<const uint4*>(g_feats16 + (size_t)n * CIN + s * 8);
        *reinterpret_cast<uint4*>(As + r * P1 + s * 8) = v;
    }
    // stage B: 64 rows x 96 halves = 768 uint4
#pragma unroll
    for (int p = 0; p < 3; p++) {
        const int idx = tid + p * 256;
        const int r = idx / 12, s = idx % 12;
        *reinterpret_cast<uint4*>(Bs + r * P1 + s * 8) =
            *reinterpret_cast<const uint4*>(g_w1t + (size_t)(h0 + r) * CIN + s * 8);
    }
    __syncthreads();

    const int lane = tid & 31, wid = tid >> 5;
    const int wm = wid & 3, wn = wid >> 2;
    const int gid = lane >> 2, tig = lane & 3;

    float acc[2][4][4];
#pragma unroll
    for (int mi = 0; mi < 2; mi++)
#pragma unroll
        for (int ni = 0; ni < 4; ni++)
#pragma unroll
            for (int q = 0; q < 4; q++) acc[mi][ni][q] = 0.0f;

#pragma unroll
    for (int ks = 0; ks < 6; ks++) {
        const int k0 = ks * 16;
        unsigned a[2][4], b[4][2];
#pragma unroll
        for (int mi = 0; mi < 2; mi++) {
            const __half* pa = As + (wm * 32 + mi * 16 + gid) * P1 + k0 + 2 * tig;
            a[mi][0] = *reinterpret_cast<const unsigned*>(pa);
            a[mi][1] = *reinterpret_cast<const unsigned*>(pa + 8 * P1);
            a[mi][2] = *reinterpret_cast<const unsigned*>(pa + 8);
            a[mi][3] = *reinterpret_cast<const unsigned*>(pa + 8 * P1 + 8);
        }
#pragma unroll
        for (int ni = 0; ni < 4; ni++) {
            const __half* pb = Bs + (wn * 32 + ni * 8 + gid) * P1 + k0 + 2 * tig;
            b[ni][0] = *reinterpret_cast<const unsigned*>(pb);
            b[ni][1] = *reinterpret_cast<const unsigned*>(pb + 8);
        }
#pragma unroll
        for (int mi = 0; mi < 2; mi++)
#pragma unroll
            for (int ni = 0; ni < 4; ni++)
                mma16816(acc[mi][ni], a[mi], b[ni]);
    }

    // epilogue
#pragma unroll
    for (int ni = 0; ni < 4; ni++) {
        const int c = h0 + wn * 32 + ni * 8 + 2 * tig;
        const float bb0 = __ldg(b1 + c),     bb1 = __ldg(b1 + c + 1);
        const float m0  = rintf(__ldg(s1 + c)) * 256.0f;
        const float m1  = rintf(__ldg(s1 + c + 1)) * 256.0f;
#pragma unroll
        for (int mi = 0; mi < 2; mi++) {
            const int r = n0 + wm * 32 + mi * 16 + gid;
#pragma unroll
            for (int h = 0; h < 2; h++) {
                const int rr = r + h * 8;
                if (rr < NPTS) {
                    float t0 = (acc[mi][ni][2 * h]     + bb0) * m0;
                    float t1 = (acc[mi][ni][2 * h + 1] + bb1) * m1;
                    float v0 = relu6f(clamp128f(t0 * (1.0f / 65536.0f)));
                    float v1 = relu6f(clamp128f(t1 * (1.0f / 65536.0f)));
                    __half2 hv = __halves2half2(__float2half_rn(v0 * 256.0f),
                                                __float2half_rn(v1 * 256.0f));
                    *reinterpret_cast<__half2*>(g_x1s + (size_t)rr * CHID + c) = hv;
                }
            }
        }
    }
}

// ---------------------------------------------------------------------------
// Kernel 2: depthwise 3x3 sparse conv. x1s (=x1*256) fp16 -> x2 hi/lo fp16.
// 288 threads (2 channels each, half2), 64 sites/block.
// ---------------------------------------------------------------------------
__global__ __launch_bounds__(288) void k2_dw(
    const int* __restrict__ nbr, const float* __restrict__ w2,
    const float* __restrict__ b2, const float* __restrict__ s2)
{
    __shared__ int nbs[9 * 64];

    const int n0 = blockIdx.x * 64;
    const int c  = 2 * threadIdx.x;            // channel pair

    float2 wv[9];
#pragma unroll
    for (int k = 0; k < 9; k++) {
        wv[k].x = __ldg(w2 + k * CHID + c);
        wv[k].y = __ldg(w2 + k * CHID + c + 1);
    }
    const float bb0 = __ldg(b2 + c),     bb1 = __ldg(b2 + c + 1);
    const float m0  = rintf(__ldg(s2 + c)) * 256.0f;
    const float m1  = rintf(__ldg(s2 + c + 1)) * 256.0f;

    for (int idx = threadIdx.x; idx < 9 * 64; idx += 288) {
        const int k = idx / 64, j = idx % 64;
        const int n = n0 + j;
        nbs[idx] = (n < NPTS) ? __ldg(nbr + (size_t)k * NPTS + n) : -1;
    }
    __syncthreads();

    const int jmax = min(64, NPTS - n0);
    for (int j = 0; j < jmax; j++) {
        float a0 = 0.0f, a1 = 0.0f;
#pragma unroll
        for (int k = 0; k < 9; k++) {
            const int nb = nbs[k * 64 + j];     // uniform across block
            if (nb >= 0) {
                const __half2 h = *reinterpret_cast<const __half2*>(
                    g_x1s + (size_t)nb * CHID + c);
                const float2 f = __half22float2(h);
                a0 = fmaf(f.x, wv[k].x, a0);
                a1 = fmaf(f.y, wv[k].y, a1);
            }
        }
        // dw = acc/256 + b2  (all exact integer-scaled fp32)
        const float d0 = a0 * (1.0f / 256.0f) + bb0;
        const float d1 = a1 * (1.0f / 256.0f) + bb1;
        const float t0 = d0 * m0, t1 = d1 * m1;
        const float v0 = relu6f(clamp128f(t0 * (1.0f / 65536.0f)));
        const float v1 = relu6f(clamp128f(t1 * (1.0f / 65536.0f)));
        const __half h0 = __float2half_rn(v0), h1 = __float2half_rn(v1);
        const __half l0 = __float2half_rn(v0 - __half2float(h0));
        const __half l1 = __float2half_rn(v1 - __half2float(h1));
        const size_t o = (size_t)(n0 + j) * CHID + c;
        *reinterpret_cast<__half2*>(g_x2h + o) = __halves2half2(h0, h1);
        *reinterpret_cast<__half2*>(g_x2l + o) = __halves2half2(l0, l1);
    }
}

// ---------------------------------------------------------------------------
// Kernel 3: out = rm * clamp(requant((x2h+x2l) @ w3 + b3, s3)) + rr * feats
// BM=64, BN=96 (full), BK=64, 9 k-iters. 256 thr = 8 warps (2m x 4n),
// warp tile 32x24 -> per k-step: 2 A(hi)+2 A(lo) frags, 3 B frags, 12 mma.
// ---------------------------------------------------------------------------
#define P3 72    // padded row length in halves (stride 36 words == 4 mod 32 -> conflict-free)
__global__ __launch_bounds__(256) void k3_project(
    const float* __restrict__ feats, const float* __restrict__ b3,
    const float* __restrict__ s3,    const float* __restrict__ s_main,
    const float* __restrict__ s_res, float* __restrict__ out)
{
    __shared__ __half Ah[64 * P3];
    __shared__ __half Al[64 * P3];
    __shared__ __half Bs[96 * P3];

    const int n0 = blockIdx.x * 64;
    const int tid = threadIdx.x;
    const int lane = tid & 31, wid = tid >> 5;
    const int wm = wid & 1, wn = wid >> 1;      // 2m x 4n
    const int gid = lane >> 2, tig = lane & 3;

    float acc[2][3][4];
#pragma unroll
    for (int mi = 0; mi < 2; mi++)
#pragma unroll
        for (int ni = 0; ni < 3; ni++)
#pragma unroll
            for (int q = 0; q < 4; q++) acc[mi][ni][q] = 0.0f;

    for (int it = 0; it < 9; it++) {
        const int k0 = it * 64;
        // A hi/lo: 64 rows x 64 halves = 512 uint4 each -> 2/thread
#pragma unroll
        for (int p = 0; p < 2; p++) {
            const int idx = tid + p * 256;
            const int r = idx / 8, s = idx % 8;
            const int n = n0 + r;
            uint4 vh = make_uint4(0u, 0u, 0u, 0u), vl = vh;
            if (n < NPTS) {
                const size_t off = (size_t)n * CHID + k0 + s * 8;
                vh = *reinterpret_cast<const uint4*>(g_x2h + off);
                vl = *reinterpret_cast<const uint4*>(g_x2l + off);
            }
            *reinterpret_cast<uint4*>(Ah + r * P3 + s * 8) = vh;
            *reinterpret_cast<uint4*>(Al + r * P3 + s * 8) = vl;
        }
        // B: 96 rows x 64 halves = 768 uint4 -> 3/thread
#pragma unroll
        for (int p = 0; p < 3; p++) {
            const int idx = tid + p * 256;
            const int r = idx / 8, s = idx % 8;
            *reinterpret_cast<uint4*>(Bs + r * P3 + s * 8) =
                *reinterpret_cast<const uint4*>(g_w3t + (size_t)r * CHID + k0 + s * 8);
        }
        __syncthreads();

#pragma unroll
        for (int ks = 0; ks < 4; ks++) {
            const int kk = ks * 16;
            unsigned ah[2][4], al[2][4], b[3][2];
#pragma unroll
            for (int mi = 0; mi < 2; mi++) {
                const int row = wm * 32 + mi * 16 + gid;
                const __half* ph = Ah + row * P3 + kk + 2 * tig;
                ah[mi][0] = *reinterpret_cast<const unsigned*>(ph);
                ah[mi][1] = *reinterpret_cast<const unsigned*>(ph + 8 * P3);
                ah[mi][2] = *reinterpret_cast<const unsigned*>(ph + 8);
                ah[mi][3] = *reinterpret_cast<const unsigned*>(ph + 8 * P3 + 8);
                const __half* pl = Al + row * P3 + kk + 2 * tig;
                al[mi][0] = *reinterpret_cast<const unsigned*>(pl);
                al[mi][1] = *reinterpret_cast<const unsigned*>(pl + 8 * P3);
                al[mi][2] = *reinterpret_cast<const unsigned*>(pl + 8);
                al[mi][3] = *reinterpret_cast<const unsigned*>(pl + 8 * P3 + 8);
            }
#pragma unroll
            for (int ni = 0; ni < 3; ni++) {
                const __half* pb = Bs + (wn * 24 + ni * 8 + gid) * P3 + kk + 2 * tig;
                b[ni][0] = *reinterpret_cast<const unsigned*>(pb);
                b[ni][1] = *reinterpret_cast<const unsigned*>(pb + 8);
            }
#pragma unroll
            for (int mi = 0; mi < 2; mi++)
#pragma unroll
                for (int ni = 0; ni < 3; ni++) {
                    mma16816(acc[mi][ni], ah[mi], b[ni]);
                    mma16816(acc[mi][ni], al[mi], b[ni]);
                }
        }
        __syncthreads();
    }

    const float rm = rintf(__ldg(s_main)) * 256.0f;
    const float rr = rintf(__ldg(s_res)) * 256.0f;

#pragma unroll
    for (int ni = 0; ni < 3; ni++) {
        const int c = wn * 24 + ni * 8 + 2 * tig;
        const float bb0 = __ldg(b3 + c),     bb1 = __ldg(b3 + c + 1);
        const float m0  = rintf(__ldg(s3 + c)) * 256.0f;
        const float m1  = rintf(__ldg(s3 + c + 1)) * 256.0f;
#pragma unroll
        for (int mi = 0; mi < 2; mi++) {
            const int r = n0 + wm * 32 + mi * 16 + gid;
#pragma unroll
            for (int h = 0; h < 2; h++) {
                const int rr_ = r + h * 8;
                if (rr_ < NPTS) {
                    const float t0 = (acc[mi][ni][2 * h]     + bb0) * m0;
                    const float t1 = (acc[mi][ni][2 * h + 1] + bb1) * m1;
                    const float v0 = clamp128f(t0 * (1.0f / 65536.0f));
                    const float v1 = clamp128f(t1 * (1.0f / 65536.0f));
                    const float2 f = *reinterpret_cast<const float2*>(
                        feats + (size_t)rr_ * CIN + c);
                    float2 o;
                    o.x = rm * v0 + rr * f.x;
                    o.y = rm * v1 + rr * f.y;
                    *reinterpret_cast<float2*>(out + (size_t)rr_ * COUT + c) = o;
                }
            }
        }
    }
}

// ---------------------------------------------------------------------------
extern "C" void kernel_launch(void* const* d_in, const int* in_sizes, int n_in,
                              void* d_out, int out_size)
{
    const float* feats = (const float*)d_in[0];
    const int*   nbr   = (const int*)  d_in[1];
    const float* w1    = (const float*)d_in[2];
    const float* b1    = (const float*)d_in[3];
    const float* w2    = (const float*)d_in[4];
    const float* b2    = (const float*)d_in[5];
    const float* w3    = (const float*)d_in[6];
    const float* b3    = (const float*)d_in[7];
    const float* s1    = (const float*)d_in[8];
    const float* s2    = (const float*)d_in[9];
    const float* s3    = (const float*)d_in[10];
    const float* smain = (const float*)d_in[11];
    const float* sres  = (const float*)d_in[12];
    float* out = (float*)d_out;

    const int cvt_blocks = (int)(((size_t)NPTS * CIN + 255) / 256);
    k_convert<<<cvt_blocks, 256>>>(feats, w1, w3);

    k1_expand <<<dim3((NPTS + 127) / 128, CHID / 64), 256>>>(b1, s1);
    k2_dw     <<<(NPTS + 63) / 64, 288>>>(nbr, w2, b2, s2);
    k3_project<<<(NPTS + 63) / 64, 256>>>(feats, b3, s3, smain, sres, out);
}